// round 15
// baseline (speedup 1.0000x reference)
#include <cuda_runtime.h>
#include <cstdint>

#define BB 64
#define TT 512
#define HH 512
#define EE 256
#define G4 2048          // 4*H
#define NGRP 4           // independent batch groups
#define NCTAH 32         // hidden-partition CTAs per group
#define BG 16            // batches per group
#define JU 16            // hidden units per CTA
#define PH  516          // hs row pitch in floats (2064B, 16B-aligned, 4 mod 32)

// ---------------- device scratch (static: no allocations allowed) ----------------
__device__ float    g_gates[(size_t)TT * BB * G4];  // gates_x [t][b][j][gate]
__device__ float    g_h[2][BB * HH];                // double-buffered carry h [b][k]
__device__ int      g_rT[TT * BB];                  // reset transposed [t][b]
__device__ unsigned g_bar[NGRP * TT];               // per-(group,step) barrier counters

// ---------------- small asm helpers ----------------------------------------------
__device__ __forceinline__ unsigned long long pk2(float lo, float hi) {
    unsigned long long r;
    asm("mov.b64 %0, {%1,%2};" : "=l"(r) : "f"(lo), "f"(hi));
    return r;
}
__device__ __forceinline__ float2 upk2(unsigned long long v) {
    float2 r;
    asm("mov.b64 {%0,%1}, %2;" : "=f"(r.x), "=f"(r.y) : "l"(v));
    return r;
}
#define FFMA2(acc, a, b) \
    asm("fma.rn.f32x2 %0, %1, %2, %0;" : "+l"(acc) : "l"(a), "l"(b))

__device__ __forceinline__ unsigned smem_u32(const void* p) {
    return (unsigned)__cvta_generic_to_shared(p);
}
__device__ __forceinline__ unsigned long long lds_b64(unsigned addr) {
    unsigned long long r;
    asm("ld.shared.b64 %0, [%1];" : "=l"(r) : "r"(addr));
    return r;
}
__device__ __forceinline__ void lds_v2u64(unsigned addr, unsigned long long& a,
                                          unsigned long long& b) {
    asm("ld.shared.v2.u64 {%0,%1}, [%2];" : "=l"(a), "=l"(b) : "r"(addr));
}
// cp.async.cg: global(L2) -> shared, 16B, no register round-trip.
__device__ __forceinline__ void cp_async16(unsigned smem_dst, const void* gsrc) {
    asm volatile("cp.async.cg.shared.global [%0], [%1], 16;"
                 :: "r"(smem_dst), "l"(__cvta_generic_to_global(gsrc)) : "memory");
}
#define CP_COMMIT()  asm volatile("cp.async.commit_group;" ::: "memory")
#define CP_WAIT(n)   asm volatile("cp.async.wait_group " #n ";" ::: "memory")

// ---------------- init: zero state/barriers, build rT + mask output --------------
__global__ void init_kernel(const int* __restrict__ lengths,
                            const int* __restrict__ resets,
                            float* __restrict__ out_mask) {
    int idx = blockIdx.x * blockDim.x + threadIdx.x;   // 0..32767
    if (idx < NGRP * TT) g_bar[idx] = 0u;
    if (idx < BB * HH) { g_h[0][idx] = 0.f; g_h[1][idx] = 0.f; }
    int b = idx >> 9;
    int t = idx & 511;
    int rv = resets[b * TT + t];
    g_rT[t * BB + b] = rv;
    out_mask[b * TT + t] = (t < lengths[b]) ? 1.f : 0.f;
}

// ---------------- gates_x GEMM, fused embedding gather, f32x2 inner loop ---------
// Tiles [b][k] / [n][k] pitch 70 (even: 8B-aligned b64 loads; banks distinct).
__global__ __launch_bounds__(256) void gates_kernel(const int* __restrict__ inputs,
                                                    const float* __restrict__ emb,
                                                    const float* __restrict__ Wih,
                                                    const float* __restrict__ bih,
                                                    const float* __restrict__ bhh) {
    __shared__ float As[64 * 70];
    __shared__ float Bs[64 * 70];
    __shared__ int   tok[64];
    __shared__ float bias_s[64];

    const int t   = blockIdx.y;
    const int nb  = blockIdx.x;
    const int tid = threadIdx.x;
    const int tx  = tid & 15;
    const int ty  = tid >> 4;

    if (tid < 64) {
        tok[tid] = inputs[tid * TT + t];
    } else if (tid < 128) {
        int n  = nb * 64 + (tid - 64);
        int wr = (n & 3) * 512 + (n >> 2);
        bias_s[tid - 64] = bih[wr] + bhh[wr];
    }
    __syncthreads();

    const unsigned as_s = smem_u32(As);
    const unsigned bs_s = smem_u32(Bs);

    unsigned long long acc2[4][4] = {};
    for (int kc = 0; kc < EE; kc += 64) {
#pragma unroll
        for (int i = 0; i < 16; i++) {
            int idx = i * 256 + tid;
            int mi  = idx >> 6;
            int kk  = idx & 63;
            As[mi * 70 + kk] = emb[(size_t)tok[mi] * EE + kc + kk];
            int n  = nb * 64 + mi;
            int wr = (n & 3) * 512 + (n >> 2);
            Bs[mi * 70 + kk] = Wih[wr * EE + kc + kk];
        }
        __syncthreads();
#pragma unroll 8
        for (int kk = 0; kk < 64; kk += 2) {
            unsigned long long a0 = lds_b64(as_s + (unsigned)((ty * 4 + 0) * 70 + kk) * 4u);
            unsigned long long a1 = lds_b64(as_s + (unsigned)((ty * 4 + 1) * 70 + kk) * 4u);
            unsigned long long a2 = lds_b64(as_s + (unsigned)((ty * 4 + 2) * 70 + kk) * 4u);
            unsigned long long a3 = lds_b64(as_s + (unsigned)((ty * 4 + 3) * 70 + kk) * 4u);
            unsigned long long b0 = lds_b64(bs_s + (unsigned)((tx * 4 + 0) * 70 + kk) * 4u);
            unsigned long long b1 = lds_b64(bs_s + (unsigned)((tx * 4 + 1) * 70 + kk) * 4u);
            unsigned long long b2 = lds_b64(bs_s + (unsigned)((tx * 4 + 2) * 70 + kk) * 4u);
            unsigned long long b3 = lds_b64(bs_s + (unsigned)((tx * 4 + 3) * 70 + kk) * 4u);
            FFMA2(acc2[0][0], a0, b0); FFMA2(acc2[0][1], a0, b1);
            FFMA2(acc2[0][2], a0, b2); FFMA2(acc2[0][3], a0, b3);
            FFMA2(acc2[1][0], a1, b0); FFMA2(acc2[1][1], a1, b1);
            FFMA2(acc2[1][2], a1, b2); FFMA2(acc2[1][3], a1, b3);
            FFMA2(acc2[2][0], a2, b0); FFMA2(acc2[2][1], a2, b1);
            FFMA2(acc2[2][2], a2, b2); FFMA2(acc2[2][3], a2, b3);
            FFMA2(acc2[3][0], a3, b0); FFMA2(acc2[3][1], a3, b1);
            FFMA2(acc2[3][2], a3, b2); FFMA2(acc2[3][3], a3, b3);
        }
        __syncthreads();
    }

    float* gp = g_gates + (size_t)(t * 64) * G4 + nb * 64;
#pragma unroll
    for (int r = 0; r < 4; r++) {
        float4 v;
        float2 c0 = upk2(acc2[r][0]);
        float2 c1 = upk2(acc2[r][1]);
        float2 c2 = upk2(acc2[r][2]);
        float2 c3 = upk2(acc2[r][3]);
        v.x = c0.x + c0.y + bias_s[tx * 4 + 0];
        v.y = c1.x + c1.y + bias_s[tx * 4 + 1];
        v.z = c2.x + c2.y + bias_s[tx * 4 + 2];
        v.w = c3.x + c3.y + bias_s[tx * 4 + 3];
        *reinterpret_cast<float4*>(gp + (size_t)(ty * 4 + r) * G4 + tx * 4) = v;
    }
}

// ---------------- persistent LSTM scan: 4 independent groups x 32 CTAs -----------
// CTA (grp, ch) owns batches [grp*16, grp*16+16) x units [ch*16, ch*16+16).
// Thread: jl = tid>>4, bl = tid&15. Wp = 64x512 pair-packed (128 KB, staged once).
// hs = group h slice via cp.async 4-deep pipeline. Per-group 32-CTA barrier.
// NEW: gx(t+1)/rv(t+1) prefetch and d_out store moved INTO the barrier window.
__global__ __launch_bounds__(256, 1) void scan_kernel(const float* __restrict__ Whh,
                                                      const int* __restrict__ lengths,
                                                      float* __restrict__ d_out) {
    extern __shared__ float sm[];
    float* Wp = sm;                 // 256 p * 128 floats = 32768 floats (128 KB)
    float* hs = sm + 32768;         // 16 * 516 = 8256 floats (33 KB)

    const int tid = threadIdx.x;
    const int jl  = tid >> 4;      // 0..15  unit within CTA
    const int bl  = tid & 15;      // 0..15  batch within group
    const int grp = blockIdx.x >> 5;
    const int ch  = blockIdx.x & 31;
    const int j   = ch * JU + jl;
    const int b   = grp * BG + bl;

    for (int idx = tid; idx < 32768; idx += 256) {
        int par = idx & 1;
        int g   = (idx >> 1) & 3;
        int jj  = (idx >> 3) & 15;
        int p   = idx >> 7;
        Wp[idx] = Whh[((size_t)(g * 512 + ch * JU + jj)) * 512 + 2 * p + par];
    }

    float c_reg = 0.f;
    const int len_b = lengths[b];

    const float4* gx4 = reinterpret_cast<const float4*>(g_gates);
    float* hT = d_out + (size_t)BB * TT * HH;
    float* cT = hT + BB * HH;

    const unsigned hs_s  = smem_u32(hs);
    const unsigned wp_s  = smem_u32(Wp);
    const unsigned hrow  = hs_s + (unsigned)(bl * PH) * 4u;
    const unsigned wbase = wp_s + (unsigned)(jl * 8) * 4u;
    unsigned* bar = &g_bar[grp * TT];

    // prefetch step-0 operands
    float4 gx = __ldg(&gx4[(size_t)(0 * BB + b) * 512 + j]);
    int    rv = __ldg(&g_rT[0 * BB + b]);

    __syncthreads();

    for (int t = 0; t < TT; t++) {
        const float4* gh4 = reinterpret_cast<const float4*>(g_h[t & 1]);
        float*        ghw = g_h[(t + 1) & 1];

        // ---- issue group's h staging up front: 4 k-chunks = 4 commit groups ----
#pragma unroll
        for (int c2 = 0; c2 < 4; c2++) {
#pragma unroll
            for (int i = 0; i < 2; i++) {
                int idx = i * 256 + tid;       // 0..511
                int b2  = idx >> 5;            // local batch 0..15
                int q4  = idx & 31;
                cp_async16(hs_s + (unsigned)(b2 * PH + (c2 * 32 + q4) * 4) * 4u,
                           &gh4[(grp * BG + b2) * 128 + c2 * 32 + q4]);
            }
            CP_COMMIT();
        }

        unsigned long long acc0 = pk2(gx.x, 0.f);
        unsigned long long acc1 = pk2(gx.y, 0.f);
        unsigned long long acc2 = pk2(gx.z, 0.f);
        unsigned long long acc3 = pk2(gx.w, 0.f);

        // ---- 4-deep pipelined consume ----
#pragma unroll
        for (int c = 0; c < 4; c++) {
            if      (c == 0) CP_WAIT(3);
            else if (c == 1) CP_WAIT(2);
            else if (c == 2) CP_WAIT(1);
            else             CP_WAIT(0);
            __syncthreads();
#pragma unroll 16
            for (int p = c * 64; p < c * 64 + 64; p++) {
                unsigned long long h2 = lds_b64(hrow + (unsigned)(2 * p) * 4u);
                unsigned long long w0, w1, w2, w3;
                unsigned wa = wbase + (unsigned)(p * 128) * 4u;
                lds_v2u64(wa,       w0, w1);
                lds_v2u64(wa + 16u, w2, w3);
                FFMA2(acc0, h2, w0);
                FFMA2(acc1, h2, w1);
                FFMA2(acc2, h2, w2);
                FFMA2(acc3, h2, w3);
            }
        }
        float h_prev = hs[bl * PH + j];

        // ---- reduce f32x2 halves, activations, state update ----
        float2 r0 = upk2(acc0), r1 = upk2(acc1), r2 = upk2(acc2), r3 = upk2(acc3);
        float si = r0.x + r0.y;
        float sf = r1.x + r1.y;
        float sg = r2.x + r2.y;
        float so = r3.x + r3.y;

        float ig = 1.f / (1.f + __expf(-si));
        float fg = 1.f / (1.f + __expf(-sf));
        float gg = tanhf(sg);
        float og = 1.f / (1.f + __expf(-so));
        float c_new = fg * c_reg + ig * gg;
        float h_new = og * tanhf(c_new);

        float m  = (t < len_b) ? 1.f : 0.f;
        float h_nx = m * h_new + (1.f - m) * h_prev;
        float c_nx = m * c_new + (1.f - m) * c_reg;

        float rr = (float)rv;
        c_reg = c_nx * (1.f - rr);
        float h_carry = h_nx * (1.f - rr);
        ghw[b * HH + j] = h_carry;               // publish BEFORE fence

        if (t < TT - 1) {
            // ---- per-group barrier with latency-hiding window ----
            __threadfence();                      // publish ghw to GPU scope
            __syncthreads();                      // whole CTA published
            if (tid == 0) atomicAdd(&bar[t], 1u); // arrive

            // useful work inside the wait window:
            d_out[((size_t)b * TT + t) * HH + j] = h_nx;
            gx = __ldg(&gx4[(size_t)((t + 1) * BB + b) * 512 + j]);
            rv = __ldg(&g_rT[(t + 1) * BB + b]);

            if (tid == 0) {
                while (*((volatile unsigned*)&bar[t]) < (unsigned)NCTAH) {
                    __nanosleep(64);
                }
            }
            __syncthreads();
        } else {
            d_out[((size_t)b * TT + t) * HH + j] = h_nx;
            hT[b * HH + j] = h_carry;
            cT[b * HH + j] = c_reg;
        }
    }
}

// ---------------- launch ---------------------------------------------------------
extern "C" void kernel_launch(void* const* d_in, const int* in_sizes, int n_in,
                              void* d_out, int out_size) {
    const int*   inputs  = (const int*)d_in[0];
    const int*   lengths = (const int*)d_in[1];
    const int*   resets  = (const int*)d_in[2];
    const float* emb     = (const float*)d_in[3];
    const float* Wih     = (const float*)d_in[4];
    const float* Whh     = (const float*)d_in[5];
    const float* bih     = (const float*)d_in[6];
    const float* bhh     = (const float*)d_in[7];
    float* out = (float*)d_out;
    float* out_mask = out + (size_t)BB * TT * HH + 2 * (size_t)BB * HH;

    const int SMEM_SCAN = (32768 + BG * PH) * (int)sizeof(float);  // 164096 B
    cudaFuncSetAttribute(scan_kernel, cudaFuncAttributeMaxDynamicSharedMemorySize, SMEM_SCAN);

    init_kernel<<<128, 256>>>(lengths, resets, out_mask);
    gates_kernel<<<dim3(32, 512), 256>>>(inputs, emb, Wih, bih, bhh);
    scan_kernel<<<NGRP * NCTAH, 256, SMEM_SCAN>>>(Whh, lengths, out);
}